// round 5
// baseline (speedup 1.0000x reference)
#include <cuda_runtime.h>
#include <float.h>

#define BT     (16 * 512)   // 8192 pairs
#define IDIM   80
#define HDIM   512
#define NSHIFT 159          // 2*IDIM - 1
#define PAD    79
#define SKP    248          // padded keypad stride (238 + lane-tail overread)

// Scratch for x_attn (allocation-free rule: __device__ global)
__device__ float g_xattn[BT * IDIM];

__device__ __forceinline__ float warpReduceSum(float v) {
#pragma unroll
    for (int o = 16; o; o >>= 1) v += __shfl_xor_sync(0xffffffffu, v, o);
    return v;
}
__device__ __forceinline__ float warpReduceMax(float v) {
#pragma unroll
    for (int o = 16; o; o >>= 1) v = fmaxf(v, __shfl_xor_sync(0xffffffffu, v, o));
    return v;
}

// ---------------------------------------------------------------------------
// Kernel 1: warp-per-pair sliding window. R5: packed fma.rn.f32x2 — each
// 32-bit half accumulates in the SAME i-ascending order as the validated R3
// scalar version => bit-identical sims => identical argmax.
// ---------------------------------------------------------------------------
#define PAIRS_PER_BLK 8
__global__ __launch_bounds__(256) void attn_kernel(
    const float* __restrict__ x, const float* __restrict__ y,
    float* __restrict__ xattn)
{
    const int warp = threadIdx.x >> 5;
    const int lane = threadIdx.x & 31;
    const int p    = blockIdx.x * PAIRS_PER_BLK + warp;

    __shared__ float kp[PAIRS_PER_BLK][SKP];
    __shared__ float ys[PAIRS_PER_BLK][IDIM];
    float* kpw = kp[warp];
    float* ysw = ys[warp];

    for (int i = lane; i < SKP; i += 32) kpw[i] = 0.0f;
    __syncwarp();

    const float* xp = x + (size_t)p * IDIM;
    const float* yp = y + (size_t)p * IDIM;
    float yn2 = 0.0f;
    for (int i = lane; i < IDIM; i += 32) {
        kpw[PAD + i] = xp[i];
        float v = yp[i];
        ysw[i] = v;
        yn2 = fmaf(v, v, yn2);
    }
    yn2 = warpReduceSum(yn2);
    __syncwarp();

    const int base = lane * 5;
    float w0 = kpw[base + 0], w1 = kpw[base + 1], w2 = kpw[base + 2],
          w3 = kpw[base + 3], w4 = kpw[base + 4];

    unsigned long long d01 = 0ull, d23 = 0ull, q01 = 0ull, q23 = 0ull;
    float d4 = 0.0f, q4 = 0.0f;
#pragma unroll
    for (int i = 0; i < IDIM; ++i) {
        float yv = ysw[i];
        unsigned long long yv2, w01, w23;
        asm("mov.b64 %0, {%1, %2};" : "=l"(yv2) : "f"(yv), "f"(yv));
        asm("mov.b64 %0, {%1, %2};" : "=l"(w01) : "f"(w0), "f"(w1));
        asm("mov.b64 %0, {%1, %2};" : "=l"(w23) : "f"(w2), "f"(w3));
        asm("fma.rn.f32x2 %0, %1, %2, %0;" : "+l"(d01) : "l"(w01), "l"(yv2));
        asm("fma.rn.f32x2 %0, %1, %2, %0;" : "+l"(d23) : "l"(w23), "l"(yv2));
        d4 = fmaf(w4, yv, d4);
        asm("fma.rn.f32x2 %0, %1, %2, %0;" : "+l"(q01) : "l"(w01), "l"(w01));
        asm("fma.rn.f32x2 %0, %1, %2, %0;" : "+l"(q23) : "l"(w23), "l"(w23));
        q4 = fmaf(w4, w4, q4);
        w0 = w1; w1 = w2; w2 = w3; w3 = w4;
        w4 = kpw[base + 5 + i];
    }

    float dotv[5], n2v[5];
    asm("mov.b64 {%0, %1}, %2;" : "=f"(dotv[0]), "=f"(dotv[1]) : "l"(d01));
    asm("mov.b64 {%0, %1}, %2;" : "=f"(dotv[2]), "=f"(dotv[3]) : "l"(d23));
    asm("mov.b64 {%0, %1}, %2;" : "=f"(n2v[0]), "=f"(n2v[1]) : "l"(q01));
    asm("mov.b64 {%0, %1}, %2;" : "=f"(n2v[2]), "=f"(n2v[3]) : "l"(q23));
    dotv[4] = d4;  n2v[4] = q4;

    const float yn = sqrtf(yn2);
    float best = -FLT_MAX;
    int   bidx = 0;
#pragma unroll
    for (int j = 0; j < 5; ++j) {
        int s = base + j;
        if (s < NSHIFT) {
            float den = sqrtf(n2v[j]) * yn;
            float sim = (den > 0.0f) ? (dotv[j] / den) : 0.0f;
            if (sim > best) { best = sim; bidx = s; }
        }
    }
#pragma unroll
    for (int o = 16; o; o >>= 1) {
        float ov = __shfl_xor_sync(0xffffffffu, best, o);
        int   oi = __shfl_xor_sync(0xffffffffu, bidx, o);
        if (ov > best || (ov == best && oi < bidx)) { best = ov; bidx = oi; }
    }
    const int bs = bidx;

    float xa[3], sc[3];
    float m = -FLT_MAX;
#pragma unroll
    for (int t = 0; t < 3; ++t) {
        int i = lane + t * 32;
        if (i < IDIM) {
            xa[t] = kpw[bs + i];
            sc[t] = xa[t] * ysw[i];
            m = fmaxf(m, sc[t]);
        }
    }
    m = warpReduceMax(m);
    float sum = 0.0f, e[3];
#pragma unroll
    for (int t = 0; t < 3; ++t) {
        int i = lane + t * 32;
        if (i < IDIM) { e[t] = expf((sc[t] - m) * 0.1f); sum += e[t]; }
    }
    sum = warpReduceSum(sum);
    const float inv = 1.0f / sum;
#pragma unroll
    for (int t = 0; t < 3; ++t) {
        int i = lane + t * 32;
        if (i < IDIM) xattn[(size_t)p * IDIM + i] = xa[t] * (e[t] * inv);
    }
}

// ---------------------------------------------------------------------------
// Kernel 2: out[8192,512] = xattn[8192,80] @ W[512,80]^T + bias
// bf16 2-term split on mma.m16n8k16. R5: term-major mma order per mt so
// same-accumulator mmas are 4 independent mmas apart (breaks HMMA RAW chain).
// ---------------------------------------------------------------------------
#define SP 42   // uint2 (8B) stride per row: word-stride 84 => conflict-free

__device__ __forceinline__ void split2(float v0, float v1,
                                       unsigned& hp, unsigned& lp) {
    asm("cvt.rn.bf16x2.f32 %0, %1, %2;" : "=r"(hp) : "f"(v1), "f"(v0));
    float h0 = __uint_as_float(hp << 16);
    float h1 = __uint_as_float(hp & 0xFFFF0000u);
    asm("cvt.rn.bf16x2.f32 %0, %1, %2;" : "=r"(lp) : "f"(v1 - h1), "f"(v0 - h0));
}

__device__ __forceinline__ void mma_bf16(float d[4],
                                         unsigned a0, unsigned a1,
                                         unsigned a2, unsigned a3,
                                         unsigned b0, unsigned b1) {
    asm("mma.sync.aligned.m16n8k16.row.col.f32.bf16.bf16.f32 "
        "{%0,%1,%2,%3}, {%4,%5,%6,%7}, {%8,%9}, {%0,%1,%2,%3};"
        : "+f"(d[0]), "+f"(d[1]), "+f"(d[2]), "+f"(d[3])
        : "r"(a0), "r"(a1), "r"(a2), "r"(a3), "r"(b0), "r"(b1));
}

__global__ __launch_bounds__(256, 2) void gemm_kernel(
    const float* __restrict__ A, const float* __restrict__ W,
    const float* __restrict__ bias, float* __restrict__ out)
{
    extern __shared__ unsigned smem_u[];
    uint2* Ax = reinterpret_cast<uint2*>(smem_u);            // [128][SP] (hi,lo)
    uint2* Bx = reinterpret_cast<uint2*>(smem_u) + 128 * SP; // [128][SP]

    const int bn  = blockIdx.x * 128;
    const int bm  = blockIdx.y * 128;
    const int tid = threadIdx.x;
    const int warp = tid >> 5, lane = tid & 31;
    const int wm = warp >> 2;       // 0..1
    const int wn = warp & 3;        // 0..3
    const int g  = lane >> 2;
    const int t  = lane & 3;

#pragma unroll
    for (int it = 0; it < 10; ++it) {
        int idx = tid + it * 256;
        int row = idx / 20;
        int k4  = (idx % 20) * 4;
        int c   = k4 >> 1;

        float4 a = *reinterpret_cast<const float4*>(A + (size_t)(bm + row) * IDIM + k4);
        uint4 pa;
        split2(a.x, a.y, pa.x, pa.y);
        split2(a.z, a.w, pa.z, pa.w);
        *reinterpret_cast<uint4*>(&Ax[row * SP + c]) = pa;

        float4 b = *reinterpret_cast<const float4*>(W + (size_t)(bn + row) * IDIM + k4);
        uint4 pb;
        split2(b.x, b.y, pb.x, pb.y);
        split2(b.z, b.w, pb.z, pb.w);
        *reinterpret_cast<uint4*>(&Bx[row * SP + c]) = pb;
    }
    __syncthreads();

    float d[4][4][4];
#pragma unroll
    for (int mt = 0; mt < 4; ++mt)
#pragma unroll
        for (int nt = 0; nt < 4; ++nt)
#pragma unroll
            for (int r = 0; r < 4; ++r) d[mt][nt][r] = 0.0f;

    // K = 80 -> 5 chunks of k16
#pragma unroll
    for (int kc = 0; kc < 5; ++kc) {
        const int kb = kc * 8 + t;

        uint2 b0[4], b1[4];
#pragma unroll
        for (int nt = 0; nt < 4; ++nt) {
            int nr = (wn * 32 + nt * 8 + g) * SP + kb;
            b0[nt] = Bx[nr];
            b1[nt] = Bx[nr + 4];
        }

#pragma unroll
        for (int mt = 0; mt < 4; ++mt) {
            int r0 = (wm * 64 + mt * 16 + g) * SP + kb;
            uint2 a0 = Ax[r0];
            uint2 a1 = Ax[r0 + 8 * SP];
            uint2 a2 = Ax[r0 + 4];
            uint2 a3 = Ax[r0 + 8 * SP + 4];
            // term-major: same-accumulator mmas are 4 apart
#pragma unroll
            for (int nt = 0; nt < 4; ++nt)
                mma_bf16(d[mt][nt], a0.x, a1.x, a2.x, a3.x, b0[nt].x, b1[nt].x); // hi*hi
#pragma unroll
            for (int nt = 0; nt < 4; ++nt)
                mma_bf16(d[mt][nt], a0.x, a1.x, a2.x, a3.x, b0[nt].y, b1[nt].y); // hi*lo
#pragma unroll
            for (int nt = 0; nt < 4; ++nt)
                mma_bf16(d[mt][nt], a0.y, a1.y, a2.y, a3.y, b0[nt].x, b1[nt].x); // lo*hi
        }
    }

#pragma unroll
    for (int mt = 0; mt < 4; ++mt) {
#pragma unroll
        for (int nt = 0; nt < 4; ++nt) {
            int row = bm + wm * 64 + mt * 16 + g;
            int col = bn + wn * 32 + nt * 8 + 2 * t;
            float b0 = __ldg(bias + col), b1 = __ldg(bias + col + 1);
            float2 o0 = make_float2(d[mt][nt][0] + b0, d[mt][nt][1] + b1);
            float2 o1 = make_float2(d[mt][nt][2] + b0, d[mt][nt][3] + b1);
            *reinterpret_cast<float2*>(out + (size_t)row * HDIM + col) = o0;
            *reinterpret_cast<float2*>(out + (size_t)(row + 8) * HDIM + col) = o1;
        }
    }
}

extern "C" void kernel_launch(void* const* d_in, const int* in_sizes, int n_in,
                              void* d_out, int out_size)
{
    const float* x    = (const float*)d_in[0];
    const float* y    = (const float*)d_in[1];
    const float* fc1w = (const float*)d_in[2];
    const float* fc1b = (const float*)d_in[3];
    float* out = (float*)d_out;

    float* xattn = nullptr;
    cudaGetSymbolAddress((void**)&xattn, g_xattn);

    attn_kernel<<<BT / PAIRS_PER_BLK, 256>>>(x, y, xattn);

    const int smem_bytes = 2 * 128 * SP * 8;   // 86016
    cudaFuncSetAttribute(gemm_kernel,
                         cudaFuncAttributeMaxDynamicSharedMemorySize, smem_bytes);
    gemm_kernel<<<dim3(HDIM / 128, BT / 128), 256, smem_bytes>>>(xattn, fc1w, fc1b, out);
}

// round 6
// speedup vs baseline: 1.1417x; 1.1417x over previous
#include <cuda_runtime.h>
#include <float.h>

#define BT     (16 * 512)   // 8192 pairs
#define IDIM   80
#define HDIM   512
#define NSHIFT 159          // 2*IDIM - 1
#define PAD    79
#define SKP    248          // padded keypad stride (238 + lane-tail overread)

// Scratch for x_attn (allocation-free rule: __device__ global)
__device__ float g_xattn[BT * IDIM];

__device__ __forceinline__ float warpReduceSum(float v) {
#pragma unroll
    for (int o = 16; o; o >>= 1) v += __shfl_xor_sync(0xffffffffu, v, o);
    return v;
}
__device__ __forceinline__ float warpReduceMax(float v) {
#pragma unroll
    for (int o = 16; o; o >>= 1) v = fmaxf(v, __shfl_xor_sync(0xffffffffu, v, o));
    return v;
}

// ---------------------------------------------------------------------------
// Kernel 1: warp-per-pair sliding window (R4-validated dot loop).
// R6: window norms via shared-core decomposition:
//   n2[j] = headSuffix[j] + core + tailPrefix[j]   (ALL terms positive
//   => no cancellation; error class identical to validated direct fmaf).
// ---------------------------------------------------------------------------
#define PAIRS_PER_BLK 8
__global__ __launch_bounds__(256) void attn_kernel(
    const float* __restrict__ x, const float* __restrict__ y,
    float* __restrict__ xattn)
{
    const int warp = threadIdx.x >> 5;
    const int lane = threadIdx.x & 31;
    const int p    = blockIdx.x * PAIRS_PER_BLK + warp;

    __shared__ float kp[PAIRS_PER_BLK][SKP];
    __shared__ float ys[PAIRS_PER_BLK][IDIM];
    float* kpw = kp[warp];
    float* ysw = ys[warp];

    for (int i = lane; i < SKP; i += 32) kpw[i] = 0.0f;
    __syncwarp();

    const float* xp = x + (size_t)p * IDIM;
    const float* yp = y + (size_t)p * IDIM;
    float yn2 = 0.0f;
    for (int i = lane; i < IDIM; i += 32) {
        kpw[PAD + i] = xp[i];
        float v = yp[i];
        ysw[i] = v;
        yn2 = fmaf(v, v, yn2);
    }
    yn2 = warpReduceSum(yn2);
    __syncwarp();

    const int base = lane * 5;
    float w0 = kpw[base + 0], w1 = kpw[base + 1], w2 = kpw[base + 2],
          w3 = kpw[base + 3], w4 = kpw[base + 4];
    const float i0 = w0, i1 = w1, i2 = w2, i3 = w3;

    float d0 = 0, d1 = 0, d2 = 0, d3 = 0, d4 = 0, core = 0;
#pragma unroll
    for (int i = 0; i < IDIM; ++i) {
        float yv = ysw[i];
        d0 = fmaf(w0, yv, d0);
        d1 = fmaf(w1, yv, d1);
        d2 = fmaf(w2, yv, d2);
        d3 = fmaf(w3, yv, d3);
        d4 = fmaf(w4, yv, d4);
        if (i < IDIM - 4) core = fmaf(w4, w4, core);   // kp[base+4 .. base+79]^2
        w0 = w1; w1 = w2; w2 = w3; w3 = w4;
        w4 = kpw[base + 5 + i];
    }

    const float t0 = kpw[base + 80], t1 = kpw[base + 81],
                t2 = kpw[base + 82], t3 = kpw[base + 83];
    // head suffix sums (positive)
    const float H3 = i3 * i3;
    const float H2 = fmaf(i2, i2, H3);
    const float H1 = fmaf(i1, i1, H2);
    const float H0 = fmaf(i0, i0, H1);
    // tail prefix sums (positive)
    const float T1 = t0 * t0;
    const float T2 = fmaf(t1, t1, T1);
    const float T3 = fmaf(t2, t2, T2);
    const float T4 = fmaf(t3, t3, T3);

    float dotv[5] = {d0, d1, d2, d3, d4};
    float n2v[5];
    n2v[0] = H0 + core;
    n2v[1] = (H1 + core) + T1;
    n2v[2] = (H2 + core) + T2;
    n2v[3] = (H3 + core) + T3;
    n2v[4] = core + T4;

    const float yn = sqrtf(yn2);
    float best = -FLT_MAX;
    int   bidx = 0;
#pragma unroll
    for (int j = 0; j < 5; ++j) {
        int s = base + j;
        if (s < NSHIFT) {
            float den = sqrtf(n2v[j]) * yn;
            float sim = (den > 0.0f) ? (dotv[j] / den) : 0.0f;
            if (sim > best) { best = sim; bidx = s; }
        }
    }
#pragma unroll
    for (int o = 16; o; o >>= 1) {
        float ov = __shfl_xor_sync(0xffffffffu, best, o);
        int   oi = __shfl_xor_sync(0xffffffffu, bidx, o);
        if (ov > best || (ov == best && oi < bidx)) { best = ov; bidx = oi; }
    }
    const int bs = bidx;

    float xa[3], sc[3];
    float m = -FLT_MAX;
#pragma unroll
    for (int t = 0; t < 3; ++t) {
        int i = lane + t * 32;
        if (i < IDIM) {
            xa[t] = kpw[bs + i];
            sc[t] = xa[t] * ysw[i];
            m = fmaxf(m, sc[t]);
        }
    }
    m = warpReduceMax(m);
    float sum = 0.0f, e[3];
#pragma unroll
    for (int t = 0; t < 3; ++t) {
        int i = lane + t * 32;
        if (i < IDIM) { e[t] = expf((sc[t] - m) * 0.1f); sum += e[t]; }
    }
    sum = warpReduceSum(sum);
    const float inv = 1.0f / sum;
#pragma unroll
    for (int t = 0; t < 3; ++t) {
        int i = lane + t * 32;
        if (i < IDIM) xattn[(size_t)p * IDIM + i] = xa[t] * (e[t] * inv);
    }
}

// ---------------------------------------------------------------------------
// Kernel 2: out[8192,512] = xattn[8192,80] @ W[512,80]^T + bias
// bf16 2-term split on mma.m16n8k16 (R4-validated numerics/layout).
// R6: 128x64 blocks, 8 warps of 32x32 warp-tiles, 3 CTAs/SM.
// ---------------------------------------------------------------------------
#define SP 42   // uint2 (8B) stride per row: word-stride 84 => conflict-free

__device__ __forceinline__ void split2(float v0, float v1,
                                       unsigned& hp, unsigned& lp) {
    asm("cvt.rn.bf16x2.f32 %0, %1, %2;" : "=r"(hp) : "f"(v1), "f"(v0));
    float h0 = __uint_as_float(hp << 16);
    float h1 = __uint_as_float(hp & 0xFFFF0000u);
    asm("cvt.rn.bf16x2.f32 %0, %1, %2;" : "=r"(lp) : "f"(v1 - h1), "f"(v0 - h0));
}

__device__ __forceinline__ void mma_bf16(float d[4],
                                         unsigned a0, unsigned a1,
                                         unsigned a2, unsigned a3,
                                         unsigned b0, unsigned b1) {
    asm("mma.sync.aligned.m16n8k16.row.col.f32.bf16.bf16.f32 "
        "{%0,%1,%2,%3}, {%4,%5,%6,%7}, {%8,%9}, {%0,%1,%2,%3};"
        : "+f"(d[0]), "+f"(d[1]), "+f"(d[2]), "+f"(d[3])
        : "r"(a0), "r"(a1), "r"(a2), "r"(a3), "r"(b0), "r"(b1));
}

__global__ __launch_bounds__(256, 3) void gemm_kernel(
    const float* __restrict__ A, const float* __restrict__ W,
    const float* __restrict__ bias, float* __restrict__ out)
{
    extern __shared__ unsigned smem_u[];
    uint2* Ax = reinterpret_cast<uint2*>(smem_u);            // [128][SP]
    uint2* Bx = reinterpret_cast<uint2*>(smem_u) + 128 * SP; // [64][SP]

    const int bn  = blockIdx.x * 64;    // HDIM/64 = 8
    const int bm  = blockIdx.y * 128;   // BT/128 = 64
    const int tid = threadIdx.x;
    const int warp = tid >> 5, lane = tid & 31;
    const int wm = warp >> 1;       // 0..3  (32 rows each)
    const int wn = warp & 1;        // 0..1  (32 cols each)
    const int g  = lane >> 2;
    const int t  = lane & 3;

    // Fill A: 128 rows x 20 float4 = 2560 / 256 = 10 each
#pragma unroll
    for (int it = 0; it < 10; ++it) {
        int idx = tid + it * 256;
        int row = idx / 20;
        int k4  = (idx % 20) * 4;
        int c   = k4 >> 1;
        float4 a = *reinterpret_cast<const float4*>(A + (size_t)(bm + row) * IDIM + k4);
        uint4 pa;
        split2(a.x, a.y, pa.x, pa.y);
        split2(a.z, a.w, pa.z, pa.w);
        *reinterpret_cast<uint4*>(&Ax[row * SP + c]) = pa;
    }
    // Fill B: 64 rows x 20 float4 = 1280 / 256 = 5 each
#pragma unroll
    for (int it = 0; it < 5; ++it) {
        int idx = tid + it * 256;
        int row = idx / 20;
        int k4  = (idx % 20) * 4;
        int c   = k4 >> 1;
        float4 b = *reinterpret_cast<const float4*>(W + (size_t)(bn + row) * IDIM + k4);
        uint4 pb;
        split2(b.x, b.y, pb.x, pb.y);
        split2(b.z, b.w, pb.z, pb.w);
        *reinterpret_cast<uint4*>(&Bx[row * SP + c]) = pb;
    }
    __syncthreads();

    float d[2][4][4];
#pragma unroll
    for (int mt = 0; mt < 2; ++mt)
#pragma unroll
        for (int nt = 0; nt < 4; ++nt)
#pragma unroll
            for (int r = 0; r < 4; ++r) d[mt][nt][r] = 0.0f;

    // K = 80 -> 5 chunks of k16
#pragma unroll
    for (int kc = 0; kc < 5; ++kc) {
        const int kb = kc * 8 + t;

        uint2 b0[4], b1[4];
#pragma unroll
        for (int nt = 0; nt < 4; ++nt) {
            int nr = (wn * 32 + nt * 8 + g) * SP + kb;
            b0[nt] = Bx[nr];
            b1[nt] = Bx[nr + 4];
        }

#pragma unroll
        for (int mt = 0; mt < 2; ++mt) {
            int r0 = (wm * 32 + mt * 16 + g) * SP + kb;
            uint2 a0 = Ax[r0];
            uint2 a1 = Ax[r0 + 8 * SP];
            uint2 a2 = Ax[r0 + 4];
            uint2 a3 = Ax[r0 + 8 * SP + 4];
#pragma unroll
            for (int nt = 0; nt < 4; ++nt) {
                mma_bf16(d[mt][nt], a0.x, a1.x, a2.x, a3.x, b0[nt].x, b1[nt].x); // hi*hi
                mma_bf16(d[mt][nt], a0.x, a1.x, a2.x, a3.x, b0[nt].y, b1[nt].y); // hi*lo
                mma_bf16(d[mt][nt], a0.y, a1.y, a2.y, a3.y, b0[nt].x, b1[nt].x); // lo*hi
            }
        }
    }

#pragma unroll
    for (int mt = 0; mt < 2; ++mt) {
#pragma unroll
        for (int nt = 0; nt < 4; ++nt) {
            int row = bm + wm * 32 + mt * 16 + g;
            int col = bn + wn * 32 + nt * 8 + 2 * t;
            float b0 = __ldg(bias + col), b1 = __ldg(bias + col + 1);
            float2 o0 = make_float2(d[mt][nt][0] + b0, d[mt][nt][1] + b1);
            float2 o1 = make_float2(d[mt][nt][2] + b0, d[mt][nt][3] + b1);
            *reinterpret_cast<float2*>(out + (size_t)row * HDIM + col) = o0;
            *reinterpret_cast<float2*>(out + (size_t)(row + 8) * HDIM + col) = o1;
        }
    }
}

extern "C" void kernel_launch(void* const* d_in, const int* in_sizes, int n_in,
                              void* d_out, int out_size)
{
    const float* x    = (const float*)d_in[0];
    const float* y    = (const float*)d_in[1];
    const float* fc1w = (const float*)d_in[2];
    const float* fc1b = (const float*)d_in[3];
    float* out = (float*)d_out;

    float* xattn = nullptr;
    cudaGetSymbolAddress((void**)&xattn, g_xattn);

    attn_kernel<<<BT / PAIRS_PER_BLK, 256>>>(x, y, xattn);

    const int smem_bytes = (128 + 64) * SP * 8;   // 64512
    cudaFuncSetAttribute(gemm_kernel,
                         cudaFuncAttributeMaxDynamicSharedMemorySize, smem_bytes);
    gemm_kernel<<<dim3(HDIM / 64, BT / 128), 256, smem_bytes>>>(xattn, fc1w, fc1b, out);
}

// round 8
// speedup vs baseline: 1.3561x; 1.1878x over previous
#include <cuda_runtime.h>
#include <float.h>

#define BT     (16 * 512)   // 8192 pairs
#define IDIM   80
#define HDIM   512
#define NSHIFT 159
#define PAD    79
#define SKP    248

// Scratch for x_attn (allocation-free rule: __device__ global)
__device__ float g_xattn[BT * IDIM];

__device__ __forceinline__ float warpReduceSum(float v) {
#pragma unroll
    for (int o = 16; o; o >>= 1) v += __shfl_xor_sync(0xffffffffu, v, o);
    return v;
}
__device__ __forceinline__ float warpReduceMax(float v) {
#pragma unroll
    for (int o = 16; o; o >>= 1) v = fmaxf(v, __shfl_xor_sync(0xffffffffu, v, o));
    return v;
}

// ---------------------------------------------------------------------------
// Kernel 1 (UNCHANGED from R6 — validated): warp-per-pair sliding window,
// shared-core all-positive norm decomposition.
// ---------------------------------------------------------------------------
#define PAIRS_PER_BLK 8
__global__ __launch_bounds__(256) void attn_kernel(
    const float* __restrict__ x, const float* __restrict__ y,
    float* __restrict__ xattn)
{
    const int warp = threadIdx.x >> 5;
    const int lane = threadIdx.x & 31;
    const int p    = blockIdx.x * PAIRS_PER_BLK + warp;

    __shared__ float kp[PAIRS_PER_BLK][SKP];
    __shared__ float ys[PAIRS_PER_BLK][IDIM];
    float* kpw = kp[warp];
    float* ysw = ys[warp];

    for (int i = lane; i < SKP; i += 32) kpw[i] = 0.0f;
    __syncwarp();

    const float* xp = x + (size_t)p * IDIM;
    const float* yp = y + (size_t)p * IDIM;
    float yn2 = 0.0f;
    for (int i = lane; i < IDIM; i += 32) {
        kpw[PAD + i] = xp[i];
        float v = yp[i];
        ysw[i] = v;
        yn2 = fmaf(v, v, yn2);
    }
    yn2 = warpReduceSum(yn2);
    __syncwarp();

    const int base = lane * 5;
    float w0 = kpw[base + 0], w1 = kpw[base + 1], w2 = kpw[base + 2],
          w3 = kpw[base + 3], w4 = kpw[base + 4];
    const float i0 = w0, i1 = w1, i2 = w2, i3 = w3;

    float d0 = 0, d1 = 0, d2 = 0, d3 = 0, d4 = 0, core = 0;
#pragma unroll
    for (int i = 0; i < IDIM; ++i) {
        float yv = ysw[i];
        d0 = fmaf(w0, yv, d0);
        d1 = fmaf(w1, yv, d1);
        d2 = fmaf(w2, yv, d2);
        d3 = fmaf(w3, yv, d3);
        d4 = fmaf(w4, yv, d4);
        if (i < IDIM - 4) core = fmaf(w4, w4, core);
        w0 = w1; w1 = w2; w2 = w3; w3 = w4;
        w4 = kpw[base + 5 + i];
    }

    const float t0 = kpw[base + 80], t1 = kpw[base + 81],
                t2 = kpw[base + 82], t3 = kpw[base + 83];
    const float H3 = i3 * i3;
    const float H2 = fmaf(i2, i2, H3);
    const float H1 = fmaf(i1, i1, H2);
    const float H0 = fmaf(i0, i0, H1);
    const float T1 = t0 * t0;
    const float T2 = fmaf(t1, t1, T1);
    const float T3 = fmaf(t2, t2, T2);
    const float T4 = fmaf(t3, t3, T3);

    float dotv[5] = {d0, d1, d2, d3, d4};
    float n2v[5];
    n2v[0] = H0 + core;
    n2v[1] = (H1 + core) + T1;
    n2v[2] = (H2 + core) + T2;
    n2v[3] = (H3 + core) + T3;
    n2v[4] = core + T4;

    const float yn = sqrtf(yn2);
    float best = -FLT_MAX;
    int   bidx = 0;
#pragma unroll
    for (int j = 0; j < 5; ++j) {
        int s = base + j;
        if (s < NSHIFT) {
            float den = sqrtf(n2v[j]) * yn;
            float sim = (den > 0.0f) ? (dotv[j] / den) : 0.0f;
            if (sim > best) { best = sim; bidx = s; }
        }
    }
#pragma unroll
    for (int o = 16; o; o >>= 1) {
        float ov = __shfl_xor_sync(0xffffffffu, best, o);
        int   oi = __shfl_xor_sync(0xffffffffu, bidx, o);
        if (ov > best || (ov == best && oi < bidx)) { best = ov; bidx = oi; }
    }
    const int bs = bidx;

    float xa[3], sc[3];
    float m = -FLT_MAX;
#pragma unroll
    for (int t = 0; t < 3; ++t) {
        int i = lane + t * 32;
        if (i < IDIM) {
            xa[t] = kpw[bs + i];
            sc[t] = xa[t] * ysw[i];
            m = fmaxf(m, sc[t]);
        }
    }
    m = warpReduceMax(m);
    float sum = 0.0f, e[3];
#pragma unroll
    for (int t = 0; t < 3; ++t) {
        int i = lane + t * 32;
        if (i < IDIM) { e[t] = expf((sc[t] - m) * 0.1f); sum += e[t]; }
    }
    sum = warpReduceSum(sum);
    const float inv = 1.0f / sum;
#pragma unroll
    for (int t = 0; t < 3; ++t) {
        int i = lane + t * 32;
        if (i < IDIM) xattn[(size_t)p * IDIM + i] = xa[t] * (e[t] * inv);
    }
}

// ---------------------------------------------------------------------------
// Kernel 2: out[8192,512] = xattn[8192,80] @ W[512,80]^T + bias
// Single-pass tf32 mma.m16n8k8 (R3-validated layout/indexing).
// tf32 conversion done ONCE at tile fill; mainloop is pure LDS+MMA.
// Block 128x128, 8 warps (2x4), warp tile 64x32 (4x4 mma tiles).
// ---------------------------------------------------------------------------
#define SSTR 84   // smem k-stride (pad 80 -> 84: conflict-free frag loads)

__device__ __forceinline__ unsigned f2tf(float f) {
    unsigned r;
    asm("cvt.rna.tf32.f32 %0, %1;" : "=r"(r) : "f"(f));
    return r;
}

__device__ __forceinline__ void mma_tf32(float d[4], const unsigned a[4],
                                         const unsigned b[2]) {
    asm("mma.sync.aligned.m16n8k8.row.col.f32.tf32.tf32.f32 "
        "{%0,%1,%2,%3}, {%4,%5,%6,%7}, {%8,%9}, {%0,%1,%2,%3};"
        : "+f"(d[0]), "+f"(d[1]), "+f"(d[2]), "+f"(d[3])
        : "r"(a[0]), "r"(a[1]), "r"(a[2]), "r"(a[3]), "r"(b[0]), "r"(b[1]));
}

__global__ __launch_bounds__(256, 2) void gemm_kernel(
    const float* __restrict__ A, const float* __restrict__ W,
    const float* __restrict__ bias, float* __restrict__ out)
{
    extern __shared__ unsigned smem_u[];
    unsigned* As = smem_u;              // [128][SSTR] row-major (m, k) tf32 bits
    unsigned* Bs = smem_u + 128 * SSTR; // [128][SSTR] row-major (n, k) tf32 bits

    const int bn  = blockIdx.x * 128;
    const int bm  = blockIdx.y * 128;
    const int tid = threadIdx.x;
    const int warp = tid >> 5, lane = tid & 31;
    const int wm = warp >> 2;       // 0..1  (64 rows each)
    const int wn = warp & 3;        // 0..3  (32 cols each)
    const int g  = lane >> 2;       // groupID
    const int t  = lane & 3;        // threadID in group

    // Load tiles: 128 rows x 20 float4 each; convert to tf32 at fill
#pragma unroll
    for (int it = 0; it < 10; ++it) {
        int idx = tid + it * 256;
        int row = idx / 20;
        int k4  = (idx % 20) * 4;
        float4 a = *reinterpret_cast<const float4*>(A + (size_t)(bm + row) * IDIM + k4);
        uint4 ta = make_uint4(f2tf(a.x), f2tf(a.y), f2tf(a.z), f2tf(a.w));
        *reinterpret_cast<uint4*>(&As[row * SSTR + k4]) = ta;
        float4 b = *reinterpret_cast<const float4*>(W + (size_t)(bn + row) * IDIM + k4);
        uint4 tb = make_uint4(f2tf(b.x), f2tf(b.y), f2tf(b.z), f2tf(b.w));
        *reinterpret_cast<uint4*>(&Bs[row * SSTR + k4]) = tb;
    }
    __syncthreads();

    float d[4][4][4];
#pragma unroll
    for (int mt = 0; mt < 4; ++mt)
#pragma unroll
        for (int nt = 0; nt < 4; ++nt)
#pragma unroll
            for (int r = 0; r < 4; ++r) d[mt][nt][r] = 0.0f;

#pragma unroll
    for (int k0 = 0; k0 < IDIM; k0 += 8) {
        unsigned bf[4][2];
#pragma unroll
        for (int nt = 0; nt < 4; ++nt) {
            int nr = (wn * 32 + nt * 8 + g) * SSTR + k0 + t;
            bf[nt][0] = Bs[nr];
            bf[nt][1] = Bs[nr + 4];
        }
#pragma unroll
        for (int mt = 0; mt < 4; ++mt) {
            int r0 = (wm * 64 + mt * 16 + g) * SSTR + k0 + t;
            unsigned af[4];
            af[0] = As[r0];
            af[1] = As[r0 + 8 * SSTR];
            af[2] = As[r0 + 4];
            af[3] = As[r0 + 8 * SSTR + 4];
#pragma unroll
            for (int nt = 0; nt < 4; ++nt)
                mma_tf32(d[mt][nt], af, bf[nt]);
        }
    }

    // Epilogue: c0,c1 -> (row, 2t..2t+1); c2,c3 -> (row+8, 2t..2t+1)
#pragma unroll
    for (int mt = 0; mt < 4; ++mt) {
#pragma unroll
        for (int nt = 0; nt < 4; ++nt) {
            int row = bm + wm * 64 + mt * 16 + g;
            int col = bn + wn * 32 + nt * 8 + 2 * t;
            float b0 = __ldg(bias + col), b1 = __ldg(bias + col + 1);
            float2 o0 = make_float2(d[mt][nt][0] + b0, d[mt][nt][1] + b1);
            float2 o1 = make_float2(d[mt][nt][2] + b0, d[mt][nt][3] + b1);
            *reinterpret_cast<float2*>(out + (size_t)row * HDIM + col) = o0;
            *reinterpret_cast<float2*>(out + (size_t)(row + 8) * HDIM + col) = o1;
        }
    }
}

extern "C" void kernel_launch(void* const* d_in, const int* in_sizes, int n_in,
                              void* d_out, int out_size)
{
    const float* x    = (const float*)d_in[0];
    const float* y    = (const float*)d_in[1];
    const float* fc1w = (const float*)d_in[2];
    const float* fc1b = (const float*)d_in[3];
    float* out = (float*)d_out;

    float* xattn = nullptr;
    cudaGetSymbolAddress((void**)&xattn, g_xattn);

    attn_kernel<<<BT / PAIRS_PER_BLK, 256>>>(x, y, xattn);

    const int smem_bytes = 2 * 128 * SSTR * (int)sizeof(unsigned);  // 86016
    cudaFuncSetAttribute(gemm_kernel,
                         cudaFuncAttributeMaxDynamicSharedMemorySize, smem_bytes);
    gemm_kernel<<<dim3(HDIM / 128, BT / 128), 256, smem_bytes>>>(xattn, fc1w, fc1b, out);
}